// round 6
// baseline (speedup 1.0000x reference)
#include <cuda_runtime.h>

#define HID   50
#define SEQT  512
#define NB    4          // batch elements (groups) per block
#define GROUP 64         // threads per group (2 warps)
#define BLOCK (NB * GROUP)   // 256
#define ROWP  52         // padded h row (floats)

// packed 2xfp32 FMA: d = a*b + c
__device__ __forceinline__ unsigned long long fma2(unsigned long long a,
                                                   unsigned long long b,
                                                   unsigned long long c) {
    unsigned long long d;
    asm("fma.rn.f32x2 %0, %1, %2, %3;" : "=l"(d) : "l"(a), "l"(b), "l"(c));
    return d;
}
__device__ __forceinline__ float hsum2(unsigned long long v) {
    float lo, hi;
    asm("mov.b64 {%0, %1}, %2;" : "=f"(lo), "=f"(hi) : "l"(v));
    return lo + hi;
}
__device__ __forceinline__ float tanhapx(float x) {
    float y;
    asm("tanh.approx.f32 %0, %1;" : "=f"(y) : "f"(x));
    return y;
}
__device__ __forceinline__ float sigapx(float x) {
    return __fmaf_rn(0.5f, tanhapx(0.5f * x), 0.5f);
}
// named barrier over `cnt` threads (2 warps of one group)
__device__ __forceinline__ void group_bar(int id) {
    asm volatile("bar.sync %0, %1;" :: "r"(id), "n"(GROUP) : "memory");
}

__global__ void __launch_bounds__(BLOCK, 1)
lstm_fused_kernel(const float* __restrict__ x,
                  const float* __restrict__ W_ih,
                  const float* __restrict__ W_hh,
                  const float* __restrict__ b_ih,
                  const float* __restrict__ b_hh,
                  const float* __restrict__ W_out,
                  const float* __restrict__ b_out,
                  float* __restrict__ out,
                  int B)
{
    __shared__ __align__(16) float sh_h[2][NB][ROWP];   // double-buffered h
    __shared__ __align__(16) float sh_wout[ROWP];

    const int tid = threadIdx.x;
    const int g   = tid >> 6;        // group / local batch index 0..3
    const int r   = tid & 63;        // lane within group
    const int j   = r;               // hidden unit (valid when r < 50)
    const int b   = blockIdx.x * NB + g;
    const bool active = (b < B);
    const int bb = active ? b : 0;
    const bool gate_th = active && (r < HID);
    const bool out_th  = active && (r == HID);

    // ---- one-time init ----
    for (int i = tid; i < 2 * NB * ROWP; i += BLOCK)
        (&sh_h[0][0][0])[i] = 0.0f;
    if (tid < ROWP)
        sh_wout[tid] = (tid < HID) ? W_out[tid] : 0.0f;

    // gate threads: 4 W_hh rows in registers as f32 pairs (row base 8B-aligned)
    unsigned long long w2[4][25];
    float wih[4], bs[4];
    if (gate_th) {
        #pragma unroll
        for (int gg = 0; gg < 4; gg++) {
            const int row = gg * HID + j;     // PyTorch gate order: i, f, g, o
            wih[gg] = W_ih[row];
            bs[gg]  = b_ih[row] + b_hh[row];
            const unsigned long long* wrow =
                reinterpret_cast<const unsigned long long*>(W_hh + row * HID);
            #pragma unroll
            for (int p = 0; p < 25; p++)
                w2[gg][p] = wrow[p];
        }
    }
    const float bout = b_out[0];

    const float* __restrict__ xrow = x   + (size_t)bb * SEQT;
    float*       __restrict__ orow = out + (size_t)bb * SEQT;

    float c  = 0.0f;
    float xt = gate_th ? xrow[0] : 0.0f;
    int cur = 0;

    __syncthreads();   // h zeroed, wout staged (block-wide, once)

    const int barid = g + 1;   // named barrier ids 1..4

    for (int t = 0; t < SEQT; t++) {
        const int nxt = cur ^ 1;

        if (gate_th) {
            unsigned long long acc0 = 0ull, acc1 = 0ull, acc2 = 0ull, acc3 = 0ull;
            float xnext = (t + 1 < SEQT) ? xrow[t + 1] : 0.0f;

            const float* hptr = &sh_h[cur][g][0];
            #pragma unroll
            for (int q = 0; q < 12; q++) {        // h[0..47]
                const ulonglong2 hv =
                    *reinterpret_cast<const ulonglong2*>(hptr + q * 4);
                acc0 = fma2(hv.x, w2[0][2*q],   acc0);
                acc1 = fma2(hv.x, w2[1][2*q],   acc1);
                acc2 = fma2(hv.x, w2[2][2*q],   acc2);
                acc3 = fma2(hv.x, w2[3][2*q],   acc3);
                acc0 = fma2(hv.y, w2[0][2*q+1], acc0);
                acc1 = fma2(hv.y, w2[1][2*q+1], acc1);
                acc2 = fma2(hv.y, w2[2][2*q+1], acc2);
                acc3 = fma2(hv.y, w2[3][2*q+1], acc3);
            }
            {   // h[48..49]
                const unsigned long long hv =
                    *reinterpret_cast<const unsigned long long*>(hptr + 48);
                acc0 = fma2(hv, w2[0][24], acc0);
                acc1 = fma2(hv, w2[1][24], acc1);
                acc2 = fma2(hv, w2[2][24], acc2);
                acc3 = fma2(hv, w2[3][24], acc3);
            }

            const float a0 = hsum2(acc0) + __fmaf_rn(xt, wih[0], bs[0]);
            const float a1 = hsum2(acc1) + __fmaf_rn(xt, wih[1], bs[1]);
            const float a2 = hsum2(acc2) + __fmaf_rn(xt, wih[2], bs[2]);
            const float a3 = hsum2(acc3) + __fmaf_rn(xt, wih[3], bs[3]);

            const float ig = sigapx(a0);
            const float fg = sigapx(a1);
            const float gg = tanhapx(a2);
            const float og = sigapx(a3);
            c = __fmaf_rn(fg, c, ig * gg);
            const float hn = og * tanhapx(c);

            sh_h[nxt][g][j] = hn;
            xt = xnext;
        } else if (out_th && t > 0) {
            // out[t-1] = h_{t-1} . W_out + b_out ; h_{t-1} lives in buf[cur].
            // Runs concurrently with the gate threads' dot (read-read overlap).
            const float* hp = &sh_h[cur][g][0];
            float y0 = bout, y1 = 0.0f, y2 = 0.0f, y3 = 0.0f;
            #pragma unroll
            for (int kq = 0; kq < 13; kq++) {     // pads are zero in both
                const float4 hv = *reinterpret_cast<const float4*>(hp + kq * 4);
                const float4 wv = *reinterpret_cast<const float4*>(sh_wout + kq * 4);
                y0 = __fmaf_rn(hv.x, wv.x, y0);
                y1 = __fmaf_rn(hv.y, wv.y, y1);
                y2 = __fmaf_rn(hv.z, wv.z, y2);
                y3 = __fmaf_rn(hv.w, wv.w, y3);
            }
            orow[t - 1] = (y0 + y1) + (y2 + y3);
        }

        group_bar(barid);    // only this group's 2 warps
        cur = nxt;
    }

    // final output element: h_{T-1} is in buf[cur]
    if (out_th) {
        const float* hp = &sh_h[cur][g][0];
        float y0 = bout, y1 = 0.0f, y2 = 0.0f, y3 = 0.0f;
        #pragma unroll
        for (int kq = 0; kq < 13; kq++) {
            const float4 hv = *reinterpret_cast<const float4*>(hp + kq * 4);
            const float4 wv = *reinterpret_cast<const float4*>(sh_wout + kq * 4);
            y0 = __fmaf_rn(hv.x, wv.x, y0);
            y1 = __fmaf_rn(hv.y, wv.y, y1);
            y2 = __fmaf_rn(hv.z, wv.z, y2);
            y3 = __fmaf_rn(hv.w, wv.w, y3);
        }
        orow[SEQT - 1] = (y0 + y1) + (y2 + y3);
    }
}

extern "C" void kernel_launch(void* const* d_in, const int* in_sizes, int n_in,
                              void* d_out, int out_size)
{
    const float* x     = (const float*)d_in[0];
    const float* W_ih  = (const float*)d_in[1];
    const float* W_hh  = (const float*)d_in[2];
    const float* b_ih  = (const float*)d_in[3];
    const float* b_hh  = (const float*)d_in[4];
    const float* W_out = (const float*)d_in[5];
    const float* b_out = (const float*)d_in[6];
    float* out = (float*)d_out;

    const int B = in_sizes[0] / SEQT;          // I == 1, x is [B, T, 1]
    const int grid = (B + NB - 1) / NB;
    lstm_fused_kernel<<<grid, BLOCK>>>(x, W_ih, W_hh, b_ih, b_hh, W_out, b_out, out, B);
}

// round 7
// speedup vs baseline: 1.1983x; 1.1983x over previous
#include <cuda_runtime.h>

#define HID   50
#define SEQT  512
#define NG    5            // thread-groups (unit-sets) per block
#define NB    10           // batch elements per block (2 per group)
#define BLOCK 256          // 5*50 = 250 active threads
#define ROWP  52           // padded h row (floats)

// packed 2xfp32 FMA: d = a*b + c
__device__ __forceinline__ unsigned long long fma2(unsigned long long a,
                                                   unsigned long long b,
                                                   unsigned long long c) {
    unsigned long long d;
    asm("fma.rn.f32x2 %0, %1, %2, %3;" : "=l"(d) : "l"(a), "l"(b), "l"(c));
    return d;
}
__device__ __forceinline__ float hsum2(unsigned long long v) {
    float lo, hi;
    asm("mov.b64 {%0, %1}, %2;" : "=f"(lo), "=f"(hi) : "l"(v));
    return lo + hi;
}
__device__ __forceinline__ float tanhapx(float x) {
    float y;
    asm("tanh.approx.f32 %0, %1;" : "=f"(y) : "f"(x));
    return y;
}
__device__ __forceinline__ float sigapx(float x) {
    return __fmaf_rn(0.5f, tanhapx(0.5f * x), 0.5f);
}

__global__ void __launch_bounds__(BLOCK, 1)
lstm_fused_kernel(const float* __restrict__ x,
                  const float* __restrict__ W_ih,
                  const float* __restrict__ W_hh,
                  const float* __restrict__ b_ih,
                  const float* __restrict__ b_hh,
                  const float* __restrict__ W_out,
                  const float* __restrict__ b_out,
                  float* __restrict__ out,
                  int B)
{
    // h rows: elems 0..4 are stream A of groups 0..4, elems 5..9 stream B
    __shared__ __align__(16) float sh_h[2][NB][ROWP];
    __shared__ __align__(16) float sh_wout[ROWP];

    const int tid = threadIdx.x;
    int bl = tid / HID;              // group 0..4 (5 == filler lanes 250..255)
    int j  = tid - bl * HID;         // hidden unit 0..49
    const bool lane_ok = (bl < NG);
    if (!lane_ok) { bl = 0; j = 0; }
    const int b0 = blockIdx.x * NB + bl;        // stream A elem
    const int b1 = b0 + NG;                     // stream B elem
    const bool actA = lane_ok && (b0 < B);
    const bool actB = lane_ok && (b1 < B);
    const int bbA = actA ? b0 : 0;
    const int bbB = actB ? b1 : 0;

    // ---- one-time init ----
    for (int i = tid; i < 2 * NB * ROWP; i += BLOCK)
        (&sh_h[0][0][0])[i] = 0.0f;
    if (tid < ROWP)
        sh_wout[tid] = (tid < HID) ? W_out[tid] : 0.0f;

    // 4 W_hh gate rows for unit j, packed as f32 pairs (shared by both streams)
    unsigned long long w2[4][25];
    float wih[4], bs[4];
    #pragma unroll
    for (int g = 0; g < 4; g++) {
        const int row = g * HID + j;       // PyTorch gate order: i, f, g, o
        wih[g] = W_ih[row];
        bs[g]  = b_ih[row] + b_hh[row];
        const unsigned long long* wrow =
            reinterpret_cast<const unsigned long long*>(W_hh + row * HID);
        #pragma unroll
        for (int p = 0; p < 25; p++)
            w2[g][p] = wrow[p];
    }
    const float bout = b_out[0];

    const float* __restrict__ xrowA = x + (size_t)bbA * SEQT;
    const float* __restrict__ xrowB = x + (size_t)bbB * SEQT;
    float* __restrict__ orowA = out + (size_t)bbA * SEQT;
    float* __restrict__ orowB = out + (size_t)bbB * SEQT;

    float cA = 0.0f, cB = 0.0f;
    float xA = xrowA[0], xB = xrowB[0];
    int cur = 0;

    __syncthreads();

    for (int t = 0; t < SEQT; t++) {
        const int nxt = cur ^ 1;
        const float xnA = (t + 1 < SEQT) ? xrowA[t + 1] : 0.0f;
        const float xnB = (t + 1 < SEQT) ? xrowB[t + 1] : 0.0f;

        const float* hA = &sh_h[cur][bl][0];        // stream B row at +NG*ROWP
        unsigned long long a0 = 0ull, a1 = 0ull, a2 = 0ull, a3 = 0ull;
        unsigned long long e0 = 0ull, e1 = 0ull, e2 = 0ull, e3 = 0ull;

        // interleaved dual-stream dot product: 2 x 104 fma2
        #pragma unroll
        for (int q = 0; q < 12; q++) {
            const ulonglong2 hvA = *reinterpret_cast<const ulonglong2*>(hA + q * 4);
            const ulonglong2 hvB = *reinterpret_cast<const ulonglong2*>(hA + NG * ROWP + q * 4);
            a0 = fma2(hvA.x, w2[0][2*q],   a0);
            e0 = fma2(hvB.x, w2[0][2*q],   e0);
            a1 = fma2(hvA.x, w2[1][2*q],   a1);
            e1 = fma2(hvB.x, w2[1][2*q],   e1);
            a2 = fma2(hvA.x, w2[2][2*q],   a2);
            e2 = fma2(hvB.x, w2[2][2*q],   e2);
            a3 = fma2(hvA.x, w2[3][2*q],   a3);
            e3 = fma2(hvB.x, w2[3][2*q],   e3);
            a0 = fma2(hvA.y, w2[0][2*q+1], a0);
            e0 = fma2(hvB.y, w2[0][2*q+1], e0);
            a1 = fma2(hvA.y, w2[1][2*q+1], a1);
            e1 = fma2(hvB.y, w2[1][2*q+1], e1);
            a2 = fma2(hvA.y, w2[2][2*q+1], a2);
            e2 = fma2(hvB.y, w2[2][2*q+1], e2);
            a3 = fma2(hvA.y, w2[3][2*q+1], a3);
            e3 = fma2(hvB.y, w2[3][2*q+1], e3);
        }
        {
            const unsigned long long hvA =
                *reinterpret_cast<const unsigned long long*>(hA + 48);
            const unsigned long long hvB =
                *reinterpret_cast<const unsigned long long*>(hA + NG * ROWP + 48);
            a0 = fma2(hvA, w2[0][24], a0);
            e0 = fma2(hvB, w2[0][24], e0);
            a1 = fma2(hvA, w2[1][24], a1);
            e1 = fma2(hvB, w2[1][24], e1);
            a2 = fma2(hvA, w2[2][24], a2);
            e2 = fma2(hvB, w2[2][24], e2);
            a3 = fma2(hvA, w2[3][24], a3);
            e3 = fma2(hvB, w2[3][24], e3);
        }

        // stream A cell update
        {
            const float g0 = hsum2(a0) + __fmaf_rn(xA, wih[0], bs[0]);
            const float g1 = hsum2(a1) + __fmaf_rn(xA, wih[1], bs[1]);
            const float g2 = hsum2(a2) + __fmaf_rn(xA, wih[2], bs[2]);
            const float g3 = hsum2(a3) + __fmaf_rn(xA, wih[3], bs[3]);
            const float ig = sigapx(g0), fg = sigapx(g1);
            const float gg = tanhapx(g2), og = sigapx(g3);
            cA = __fmaf_rn(fg, cA, ig * gg);
            const float hn = og * tanhapx(cA);
            if (actA) sh_h[nxt][bl][j] = hn;
        }
        // stream B cell update
        {
            const float g0 = hsum2(e0) + __fmaf_rn(xB, wih[0], bs[0]);
            const float g1 = hsum2(e1) + __fmaf_rn(xB, wih[1], bs[1]);
            const float g2 = hsum2(e2) + __fmaf_rn(xB, wih[2], bs[2]);
            const float g3 = hsum2(e3) + __fmaf_rn(xB, wih[3], bs[3]);
            const float ig = sigapx(g0), fg = sigapx(g1);
            const float gg = tanhapx(g2), og = sigapx(g3);
            cB = __fmaf_rn(fg, cB, ig * gg);
            const float hn = og * tanhapx(cB);
            if (actB) sh_h[nxt][bl + NG][j] = hn;
        }
        __syncthreads();

        // output projections (unit-0 thread of each group, both streams)
        if (j == 0 && lane_ok) {
            if (actA) {
                const float* hp = &sh_h[nxt][bl][0];
                float y0 = bout, y1 = 0.0f, y2 = 0.0f, y3 = 0.0f;
                #pragma unroll
                for (int kq = 0; kq < 13; kq++) {
                    const float4 hv = *reinterpret_cast<const float4*>(hp + kq * 4);
                    const float4 wv = *reinterpret_cast<const float4*>(sh_wout + kq * 4);
                    y0 = __fmaf_rn(hv.x, wv.x, y0);
                    y1 = __fmaf_rn(hv.y, wv.y, y1);
                    y2 = __fmaf_rn(hv.z, wv.z, y2);
                    y3 = __fmaf_rn(hv.w, wv.w, y3);
                }
                orowA[t] = (y0 + y1) + (y2 + y3);
            }
            if (actB) {
                const float* hp = &sh_h[nxt][bl + NG][0];
                float y0 = bout, y1 = 0.0f, y2 = 0.0f, y3 = 0.0f;
                #pragma unroll
                for (int kq = 0; kq < 13; kq++) {
                    const float4 hv = *reinterpret_cast<const float4*>(hp + kq * 4);
                    const float4 wv = *reinterpret_cast<const float4*>(sh_wout + kq * 4);
                    y0 = __fmaf_rn(hv.x, wv.x, y0);
                    y1 = __fmaf_rn(hv.y, wv.y, y1);
                    y2 = __fmaf_rn(hv.z, wv.z, y2);
                    y3 = __fmaf_rn(hv.w, wv.w, y3);
                }
                orowB[t] = (y0 + y1) + (y2 + y3);
            }
        }

        xA = xnA;
        xB = xnB;
        cur = nxt;
    }
}

extern "C" void kernel_launch(void* const* d_in, const int* in_sizes, int n_in,
                              void* d_out, int out_size)
{
    const float* x     = (const float*)d_in[0];
    const float* W_ih  = (const float*)d_in[1];
    const float* W_hh  = (const float*)d_in[2];
    const float* b_ih  = (const float*)d_in[3];
    const float* b_hh  = (const float*)d_in[4];
    const float* W_out = (const float*)d_in[5];
    const float* b_out = (const float*)d_in[6];
    float* out = (float*)d_out;

    const int B = in_sizes[0] / SEQT;          // I == 1, x is [B, T, 1]
    const int grid = (B + NB - 1) / NB;
    lstm_fused_kernel<<<grid, BLOCK>>>(x, W_ih, W_hh, b_ih, b_hh, W_out, b_out, out, B);
}